// round 13
// baseline (speedup 1.0000x reference)
#include <cuda_runtime.h>
#include <cuda_fp16.h>
#include <cstdint>

#define NCTA 128
#define OFF_STA 131072                  // after 128KB resident w
#define SMEM_MAIN (131072 + 3 * 32768)  // 229376 (< 232448 cap)

// ---------------- device scratch ----------------
__device__ __align__(128) unsigned char g_hpack[1048576]; // [b1024][k512] fp16 h
__device__ __align__(128) unsigned char g_wpack[2097152]; // [n2048 perm][k512] fp16 w
__device__ float g_xT[512 * 1024];
__device__ float g_xdec[48 * 1024];
__device__ __align__(128) unsigned g_cnt8[256];   // 8 group counters, 128B apart

__device__ __forceinline__ float tanha(float x) {
    float r;
    asm("tanh.approx.f32 %0, %1;" : "=f"(r) : "f"(x));
    return r;
}
__device__ __forceinline__ uint32_t h2tanh(uint32_t x) {
    uint32_t r;
    asm("tanh.approx.f16x2 %0, %1;" : "=r"(r) : "r"(x));
    return r;
}
__device__ __forceinline__ uint32_t packh2(float a, float b) {
    __half2 p = __floats2half2_rn(a, b);
    return *reinterpret_cast<uint32_t*>(&p);
}
__device__ __forceinline__ float2 unpkh2(uint32_t u) {
    return __half22float2(*reinterpret_cast<__half2*>(&u));
}
__device__ __forceinline__ void cpa16(unsigned dst, const void* src) {
    asm volatile("cp.async.cg.shared.global [%0], [%1], 16;" :: "r"(dst), "l"(src));
}
__device__ __forceinline__ void ldmx4(uint32_t& r0, uint32_t& r1, uint32_t& r2,
                                      uint32_t& r3, unsigned a) {
    asm volatile("ldmatrix.sync.aligned.m8n8.x4.shared.b16 {%0,%1,%2,%3}, [%4];"
        : "=r"(r0), "=r"(r1), "=r"(r2), "=r"(r3) : "r"(a));
}
__device__ __forceinline__ void mma16816(float* d, const uint32_t* a,
                                         uint32_t b0, uint32_t b1) {
    asm volatile("mma.sync.aligned.m16n8k16.row.col.f32.f16.f16.f32 "
        "{%0,%1,%2,%3}, {%4,%5,%6,%7}, {%8,%9}, {%0,%1,%2,%3};"
        : "+f"(d[0]), "+f"(d[1]), "+f"(d[2]), "+f"(d[3])
        : "r"(a[0]), "r"(a[1]), "r"(a[2]), "r"(a[3]), "r"(b0), "r"(b1));
}

// ---------------- merged prologue kernel ----------------
extern "C" __global__ void prep_all(const float* __restrict__ x,
                                    const float* __restrict__ w_hh) {
    int bid = blockIdx.x, tid = threadIdx.x;
    int n = bid * 256 + tid;                        // 0..524287
    int b = n >> 9, t = n & 511;
    g_xT[t * 1024 + b] = x[n];                      // x[b][t][0]
    if (n < 262144) ((uint32_t*)g_hpack)[n] = 0u;   // zero h plane (1MB)
    if (n < 48 * 1024) g_xdec[n] = 0.f;
    if (n < 256) g_cnt8[n] = 0u;                    // reset group barriers
    // w pack: packed row = bid
    int ng = bid;
    int j = ng >> 7, nl = ng & 127;
    int wn = nl >> 5, gate = (nl >> 3) & 3, ul = nl & 7;
    int row = gate * 512 + j * 32 + wn * 8 + ul;
    ((__half*)g_wpack)[(size_t)ng * 512 + tid] =
        __float2half_rn(w_hh[row * 512 + tid]);
    ((__half*)g_wpack)[(size_t)ng * 512 + tid + 256] =
        __float2half_rn(w_hh[row * 512 + tid + 256]);
}

// ---------------- main persistent kernel ----------------
extern "C" __global__ void __launch_bounds__(256, 1)
lstm_mma(const float* __restrict__ w_ih, const float* __restrict__ b_ih,
         const float* __restrict__ b_hh, const float* __restrict__ w_fc,
         const float* __restrict__ b_fc, float* __restrict__ dout)
{
    extern __shared__ __align__(1024) char smem[];
    const unsigned sa = (unsigned)__cvta_generic_to_shared(smem);

    const int tid = threadIdx.x;
    const int lane = tid & 31, w = tid >> 5;
    const int wm = w >> 2, wn = w & 3;
    const int ql = lane & 3, qr = lane >> 2;
    const int i = blockIdx.x & 7, j = blockIdx.x >> 3;
    unsigned* const cptr = g_cnt8 + (i << 5);

    // per-thread constants: bias, w_ih, w_fc for its 2 units x 4 gates
    float bs[4][2], ws[4][2], wfc_r[2];
    #pragma unroll
    for (int d = 0; d < 2; ++d) {
        int u = j * 32 + wn * 8 + 2 * ql + d;
        wfc_r[d] = w_fc[u];
        #pragma unroll
        for (int g = 0; g < 4; ++g) {
            int row = g * 512 + u;
            bs[g][d] = b_ih[row] + b_hh[row];
            ws[g][d] = w_ih[row];
        }
    }
    const float bfc = b_fc[0];
    int bth[4][2];
    #pragma unroll
    for (int mt = 0; mt < 4; ++mt)
        #pragma unroll
        for (int hh = 0; hh < 2; ++hh)
            bth[mt][hh] = i * 128 + wm * 64 + mt * 16 + qr + 8 * hh;
    const int kpos = j * 32 + wn * 8 + 2 * ql;

    // ---- resident w: 8 panels of [128 rows][64 k] fp16, SW128 swizzled ----
    for (int idx = tid; idx < 8192; idx += 256) {
        int c = idx >> 10, r = (idx >> 3) & 127, q = idx & 7;
        unsigned dst = sa + (unsigned)(c * 16384 + r * 128 + ((q ^ (r & 7)) * 16));
        const char* src = (const char*)g_wpack +
            ((size_t)(j * 128 + r)) * 1024 + c * 128 + q * 16;
        cpa16(dst, src);
    }
    asm volatile("cp.async.commit_group;\n\tcp.async.wait_group 0;" ::: "memory");
    __syncthreads();

    // A staging: chunk = 128 rows x 256B (k128), 2 panels of 128B, 3-slot ring
    const int sr = tid >> 1, sq = tid & 1;
    const char* pA0 = (const char*)g_hpack +
        (size_t)(i * 128 + sr) * 1024 + sq * 128;
    const unsigned sdst = sa + OFF_STA + (unsigned)(sq * 16384 + sr * 128);
    unsigned swo[8];
    #pragma unroll
    for (int qq = 0; qq < 8; ++qq)
        swo[qq] = (unsigned)((qq ^ (sr & 7)) << 4);

    // ldmatrix thread bases
    const int rl = lane & 15, qsel = lane >> 4, sw7 = rl & 7;
    const unsigned thA = (unsigned)((wm * 64 + rl) * 128);
    const unsigned thB = (unsigned)((wn * 32 + rl) * 128);

    float cst[4][4];
    #pragma unroll
    for (int mt = 0; mt < 4; ++mt)
        #pragma unroll
        for (int e = 0; e < 4; ++e) cst[mt][e] = 0.f;

    #define LOADCHUNK(c, s) do {                                              \
        unsigned _db = sdst + (unsigned)((s) * 32768);                         \
        const char* _a0 = pA0 + (c) * 256;                                     \
        _Pragma("unroll")                                                      \
        for (int qq = 0; qq < 8; ++qq)                                         \
            cpa16(_db + swo[qq], _a0 + qq * 16);                               \
        asm volatile("cp.async.commit_group;" ::: "memory");                   \
    } while (0)

    for (int t = 0; t < 560; ++t) {
        // encoder x loads: static data, hoisted above the barrier wait
        float xtv[4][2];
        if (t < 512) {
            #pragma unroll
            for (int mt = 0; mt < 4; ++mt)
                #pragma unroll
                for (int hh = 0; hh < 2; ++hh)
                    xtv[mt][hh] = g_xT[t * 1024 + bth[mt][hh]];
        }

        // ---- group barrier wait ----
        if (t > 0) {
            if (tid == 0) {
                unsigned tgt = (unsigned)(t << 4);
                unsigned v;
                do {
                    asm volatile("ld.acquire.gpu.global.u32 %0, [%1];"
                                 : "=r"(v) : "l"(cptr) : "memory");
                    if (v < tgt) __nanosleep(32);
                } while (v < tgt);
            }
            __syncthreads();
        }

        LOADCHUNK(0, 0);
        LOADCHUNK(1, 1);

        if (t >= 512) {
            int p = t - 512;
            #pragma unroll
            for (int mt = 0; mt < 4; ++mt)
                #pragma unroll
                for (int hh = 0; hh < 2; ++hh) {
                    xtv[mt][hh] = g_xdec[p * 1024 + bth[mt][hh]] + bfc;
                    if (j == 0 && wn == 0 && ql == 0)
                        dout[bth[mt][hh] * 48 + p] = xtv[mt][hh];
                }
            if (t == 559) break;
        }

        float D[4][4][4];
        #pragma unroll
        for (int mt = 0; mt < 4; ++mt)
            #pragma unroll
            for (int nt = 0; nt < 4; ++nt)
                #pragma unroll
                for (int e = 0; e < 4; ++e) D[mt][nt][e] = 0.f;

        // ---- GEMM: 4 k128 chunks, 3-slot ring, one sync per chunk ----
        #pragma unroll 1
        for (int c = 0; c < 4; ++c) {
            if (c < 3)
                asm volatile("cp.async.wait_group 1;" ::: "memory");
            else
                asm volatile("cp.async.wait_group 0;" ::: "memory");
            __syncthreads();
            if (c < 2) LOADCHUNK(c + 2, (c + 2) % 3);
            const unsigned slotA = sa + OFF_STA + (unsigned)((c % 3) * 32768);
            #pragma unroll
            for (int k16 = 0; k16 < 8; ++k16) {
                int kw = k16 & 3, kp = k16 >> 2;
                unsigned swz = (unsigned)((((kw * 2 + qsel) ^ sw7)) << 4);
                const unsigned stB = sa + (unsigned)((c * 2 + kp) * 16384);
                const unsigned stA = slotA + (unsigned)(kp * 16384);
                uint32_t Bf[4][2];
                #pragma unroll
                for (int nb = 0; nb < 2; ++nb) {
                    uint32_t r0, r1, r2, r3;
                    ldmx4(r0, r1, r2, r3, stB + thB + nb * 2048 + swz);
                    Bf[2 * nb][0] = r0; Bf[2 * nb][1] = r2;
                    Bf[2 * nb + 1][0] = r1; Bf[2 * nb + 1][1] = r3;
                }
                #pragma unroll
                for (int mt = 0; mt < 4; ++mt) {
                    uint32_t a[4];
                    ldmx4(a[0], a[1], a[2], a[3], stA + thA + mt * 2048 + swz);
                    #pragma unroll
                    for (int nt = 0; nt < 4; ++nt)
                        mma16816(D[mt][nt], a, Bf[nt][0], Bf[nt][1]);
                }
            }
        }

        // ---- epilogue: f16x2 gate nonlinearities, fp32 c-state ----
        #pragma unroll
        for (int mt = 0; mt < 4; ++mt) {
            #pragma unroll
            for (int hh = 0; hh < 2; ++hh) {
                float xt = xtv[mt][hh];
                int e0 = 2 * hh, e1 = 2 * hh + 1;
                float gi0 = D[mt][0][e0] + bs[0][0] + xt * ws[0][0];
                float gi1 = D[mt][0][e1] + bs[0][1] + xt * ws[0][1];
                float gf0 = D[mt][1][e0] + bs[1][0] + xt * ws[1][0];
                float gf1 = D[mt][1][e1] + bs[1][1] + xt * ws[1][1];
                float gg0 = D[mt][2][e0] + bs[2][0] + xt * ws[2][0];
                float gg1 = D[mt][2][e1] + bs[2][1] + xt * ws[2][1];
                float go0 = D[mt][3][e0] + bs[3][0] + xt * ws[3][0];
                float go1 = D[mt][3][e1] + bs[3][1] + xt * ws[3][1];
                float2 fi = unpkh2(h2tanh(packh2(gi0 * 0.5f, gi1 * 0.5f)));
                float2 ff = unpkh2(h2tanh(packh2(gf0 * 0.5f, gf1 * 0.5f)));
                float2 fo = unpkh2(h2tanh(packh2(go0 * 0.5f, go1 * 0.5f)));
                float2 fg = unpkh2(h2tanh(packh2(gg0, gg1)));
                float hv2[2];
                {
                    float si = fmaf(fi.x, 0.5f, 0.5f);
                    float sf = fmaf(ff.x, 0.5f, 0.5f);
                    float so = fmaf(fo.x, 0.5f, 0.5f);
                    float c2 = sf * cst[mt][e0] + si * fg.x;
                    cst[mt][e0] = c2;
                    hv2[0] = so * tanha(c2);
                }
                {
                    float si = fmaf(fi.y, 0.5f, 0.5f);
                    float sf = fmaf(ff.y, 0.5f, 0.5f);
                    float so = fmaf(fo.y, 0.5f, 0.5f);
                    float c2 = sf * cst[mt][e1] + si * fg.y;
                    cst[mt][e1] = c2;
                    hv2[1] = so * tanha(c2);
                }
                uint32_t hiu = packh2(hv2[0], hv2[1]);
                size_t off = (size_t)bth[mt][hh] * 1024 + (size_t)kpos * 2;
                *(uint32_t*)((char*)g_hpack + off) = hiu;

                if (t >= 511) {
                    float pa = hv2[0] * wfc_r[0] + hv2[1] * wfc_r[1];
                    pa += __shfl_xor_sync(0xFFFFFFFFu, pa, 1);
                    pa += __shfl_xor_sync(0xFFFFFFFFu, pa, 2);
                    if (ql == 0)
                        atomicAdd(&g_xdec[(t - 511) * 1024 + bth[mt][hh]], pa);
                }
            }
        }

        // ---- group barrier arrive ----
        __syncthreads();
        if (tid == 0)
            asm volatile("red.release.gpu.global.add.u32 [%0], 1;"
                         :: "l"(cptr) : "memory");
    }
    #undef LOADCHUNK
}

extern "C" void kernel_launch(void* const* d_in, const int* in_sizes, int n_in,
                              void* d_out, int out_size) {
    (void)in_sizes; (void)n_in; (void)out_size;
    cudaFuncSetAttribute(lstm_mma, cudaFuncAttributeMaxDynamicSharedMemorySize,
                         SMEM_MAIN);
    prep_all<<<2048, 256>>>((const float*)d_in[0], (const float*)d_in[2]);
    lstm_mma<<<NCTA, 256, SMEM_MAIN>>>(
        (const float*)d_in[1],   // w_ih
        (const float*)d_in[3],   // b_ih
        (const float*)d_in[4],   // b_hh
        (const float*)d_in[5],   // w_fc
        (const float*)d_in[6],   // b_fc
        (float*)d_out);
}

// round 14
// speedup vs baseline: 1.2438x; 1.2438x over previous
#include <cuda_runtime.h>
#include <cuda_fp16.h>
#include <cstdint>

#define NCTA 128
#define NTHR 512
#define OFF_STA 131072                 // after 128KB resident w
#define SMEM_MAIN (131072 + 3 * 16384) // 180224

// ---------------- device scratch ----------------
__device__ __align__(128) unsigned char g_hpack[1048576]; // [b1024][k512] fp16 h
__device__ __align__(128) unsigned char g_wpack[2097152]; // [n2048 perm][k512] fp16 w
__device__ float g_xT[512 * 1024];
__device__ float g_xdec[48 * 1024];
__device__ __align__(128) unsigned g_cnt8[256];   // 8 group counters, 128B apart

__device__ __forceinline__ float tanha(float x) {
    float r;
    asm("tanh.approx.f32 %0, %1;" : "=f"(r) : "f"(x));
    return r;
}
__device__ __forceinline__ float sigm(float x) {
    return fmaf(tanha(0.5f * x), 0.5f, 0.5f);
}
__device__ __forceinline__ void cpa16(unsigned dst, const void* src) {
    asm volatile("cp.async.cg.shared.global [%0], [%1], 16;" :: "r"(dst), "l"(src));
}
__device__ __forceinline__ void ldmx4(uint32_t& r0, uint32_t& r1, uint32_t& r2,
                                      uint32_t& r3, unsigned a) {
    asm volatile("ldmatrix.sync.aligned.m8n8.x4.shared.b16 {%0,%1,%2,%3}, [%4];"
        : "=r"(r0), "=r"(r1), "=r"(r2), "=r"(r3) : "r"(a));
}
__device__ __forceinline__ void mma16816(float* d, const uint32_t* a,
                                         uint32_t b0, uint32_t b1) {
    asm volatile("mma.sync.aligned.m16n8k16.row.col.f32.f16.f16.f32 "
        "{%0,%1,%2,%3}, {%4,%5,%6,%7}, {%8,%9}, {%0,%1,%2,%3};"
        : "+f"(d[0]), "+f"(d[1]), "+f"(d[2]), "+f"(d[3])
        : "r"(a[0]), "r"(a[1]), "r"(a[2]), "r"(a[3]), "r"(b0), "r"(b1));
}

// ---------------- merged prologue kernel ----------------
extern "C" __global__ void prep_all(const float* __restrict__ x,
                                    const float* __restrict__ w_hh) {
    int bid = blockIdx.x, tid = threadIdx.x;
    int n = bid * 256 + tid;                        // 0..524287
    int b = n >> 9, t = n & 511;
    g_xT[t * 1024 + b] = x[n];                      // x[b][t][0]
    if (n < 262144) ((uint32_t*)g_hpack)[n] = 0u;   // zero h plane (1MB)
    if (n < 48 * 1024) g_xdec[n] = 0.f;
    if (n < 256) g_cnt8[n] = 0u;                    // reset group barriers
    // w pack: packed row = bid
    int ng = bid;
    int j = ng >> 7, nl = ng & 127;
    int wn = nl >> 5, gate = (nl >> 3) & 3, ul = nl & 7;
    int row = gate * 512 + j * 32 + wn * 8 + ul;
    ((__half*)g_wpack)[(size_t)ng * 512 + tid] =
        __float2half_rn(w_hh[row * 512 + tid]);
    ((__half*)g_wpack)[(size_t)ng * 512 + tid + 256] =
        __float2half_rn(w_hh[row * 512 + tid + 256]);
}

// ---------------- main persistent kernel ----------------
extern "C" __global__ void __launch_bounds__(NTHR, 1)
lstm_mma(const float* __restrict__ w_ih, const float* __restrict__ b_ih,
         const float* __restrict__ b_hh, const float* __restrict__ w_fc,
         const float* __restrict__ b_fc, float* __restrict__ dout)
{
    extern __shared__ __align__(1024) char smem[];
    const unsigned sa = (unsigned)__cvta_generic_to_shared(smem);

    const int tid = threadIdx.x;
    const int lane = tid & 31, w = tid >> 5;   // 16 warps
    const int wm = w >> 2, wn = w & 3;         // 4x4 warp grid, m32 x n32 tiles
    const int ql = lane & 3, qr = lane >> 2;
    const int i = blockIdx.x & 7, j = blockIdx.x >> 3;
    unsigned* const cptr = g_cnt8 + (i << 5);

    // per-thread constants: bias, w_ih, w_fc for its 2 units x 4 gates
    float bs[4][2], ws[4][2], wfc_r[2];
    #pragma unroll
    for (int d = 0; d < 2; ++d) {
        int u = j * 32 + wn * 8 + 2 * ql + d;
        wfc_r[d] = w_fc[u];
        #pragma unroll
        for (int g = 0; g < 4; ++g) {
            int row = g * 512 + u;
            bs[g][d] = b_ih[row] + b_hh[row];
            ws[g][d] = w_ih[row];
        }
    }
    const float bfc = b_fc[0];
    int bth[2][2];
    #pragma unroll
    for (int mt = 0; mt < 2; ++mt)
        #pragma unroll
        for (int hh = 0; hh < 2; ++hh)
            bth[mt][hh] = i * 128 + wm * 32 + mt * 16 + qr + 8 * hh;
    const int kpos = j * 32 + wn * 8 + 2 * ql;

    // ---- resident w: 8 panels of [128 rows][64 k] fp16, SW128 swizzled ----
    for (int idx = tid; idx < 8192; idx += NTHR) {
        int c = idx >> 10, r = (idx >> 3) & 127, q = idx & 7;
        unsigned dst = sa + (unsigned)(c * 16384 + r * 128 + ((q ^ (r & 7)) * 16));
        const char* src = (const char*)g_wpack +
            ((size_t)(j * 128 + r)) * 1024 + c * 128 + q * 16;
        cpa16(dst, src);
    }
    asm volatile("cp.async.commit_group;\n\tcp.async.wait_group 0;" ::: "memory");
    __syncthreads();

    // A staging: chunk = 128 rows x 128B (k64), 3-slot ring; 2x16B per thread
    const int sr = tid >> 2, sq = tid & 3;
    const char* pA0 = (const char*)g_hpack + (size_t)(i * 128 + sr) * 1024 + sq * 32;
    const unsigned sdst = sa + OFF_STA + (unsigned)(sr * 128);
    const unsigned swo0 = (unsigned)((((sq * 2)     ^ (sr & 7))) << 4);
    const unsigned swo1 = (unsigned)((((sq * 2 + 1) ^ (sr & 7))) << 4);

    // ldmatrix thread bases
    const int rl = lane & 15, qsel = lane >> 4, sw7 = rl & 7;
    const unsigned thA = (unsigned)((wm * 32 + rl) * 128);
    const unsigned thB = (unsigned)((wn * 32 + rl) * 128);

    float cst[2][4];
    #pragma unroll
    for (int mt = 0; mt < 2; ++mt)
        #pragma unroll
        for (int e = 0; e < 4; ++e) cst[mt][e] = 0.f;

    #define LOADCHUNK(c, s) do {                                              \
        unsigned _db = sdst + (unsigned)((s) * 16384);                         \
        const char* _a0 = pA0 + (c) * 128;                                     \
        cpa16(_db + swo0, _a0);                                                \
        cpa16(_db + swo1, _a0 + 16);                                           \
        asm volatile("cp.async.commit_group;" ::: "memory");                   \
    } while (0)

    for (int t = 0; t < 560; ++t) {
        // encoder x loads: static data, hoisted above the barrier wait
        float xtv[2][2];
        if (t < 512) {
            #pragma unroll
            for (int mt = 0; mt < 2; ++mt)
                #pragma unroll
                for (int hh = 0; hh < 2; ++hh)
                    xtv[mt][hh] = g_xT[t * 1024 + bth[mt][hh]];
        }

        // ---- group barrier wait ----
        if (t > 0) {
            if (tid == 0) {
                unsigned tgt = (unsigned)(t << 4);
                unsigned v;
                do {
                    asm volatile("ld.acquire.gpu.global.u32 %0, [%1];"
                                 : "=r"(v) : "l"(cptr) : "memory");
                    if (v < tgt) __nanosleep(32);
                } while (v < tgt);
            }
            __syncthreads();
        }

        LOADCHUNK(0, 0);
        LOADCHUNK(1, 1);

        if (t >= 512) {
            int p = t - 512;
            #pragma unroll
            for (int mt = 0; mt < 2; ++mt)
                #pragma unroll
                for (int hh = 0; hh < 2; ++hh) {
                    xtv[mt][hh] = g_xdec[p * 1024 + bth[mt][hh]] + bfc;
                    if (j == 0 && wn == 0 && ql == 0)
                        dout[bth[mt][hh] * 48 + p] = xtv[mt][hh];
                }
            if (t == 559) break;
        }

        float D[2][4][4];
        #pragma unroll
        for (int mt = 0; mt < 2; ++mt)
            #pragma unroll
            for (int nt = 0; nt < 4; ++nt)
                #pragma unroll
                for (int e = 0; e < 4; ++e) D[mt][nt][e] = 0.f;

        // ---- GEMM: 8 k64 chunks, 3-slot ring, one sync per chunk ----
        #pragma unroll 1
        for (int c = 0; c < 8; ++c) {
            if (c < 7)
                asm volatile("cp.async.wait_group 1;" ::: "memory");
            else
                asm volatile("cp.async.wait_group 0;" ::: "memory");
            __syncthreads();
            if (c + 2 < 8) {
                int s2 = c + 2; s2 = (s2 >= 3) ? (s2 >= 6 ? s2 - 6 : s2 - 3) : s2;
                LOADCHUNK(c + 2, s2);
            }
            int sc = (c >= 3) ? (c >= 6 ? c - 6 : c - 3) : c;
            const unsigned stA = sa + OFF_STA + (unsigned)(sc * 16384);
            const unsigned stB = sa + (unsigned)(c * 16384);
            #pragma unroll
            for (int k16 = 0; k16 < 4; ++k16) {
                unsigned swz = (unsigned)((((k16 * 2 + qsel) ^ sw7)) << 4);
                uint32_t Bf[4][2];
                #pragma unroll
                for (int nb = 0; nb < 2; ++nb) {
                    uint32_t r0, r1, r2, r3;
                    ldmx4(r0, r1, r2, r3, stB + thB + nb * 2048 + swz);
                    Bf[2 * nb][0] = r0; Bf[2 * nb][1] = r2;
                    Bf[2 * nb + 1][0] = r1; Bf[2 * nb + 1][1] = r3;
                }
                #pragma unroll
                for (int mt = 0; mt < 2; ++mt) {
                    uint32_t a[4];
                    ldmx4(a[0], a[1], a[2], a[3], stA + thA + mt * 2048 + swz);
                    #pragma unroll
                    for (int nt = 0; nt < 4; ++nt)
                        mma16816(D[mt][nt], a, Bf[nt][0], Bf[nt][1]);
                }
            }
        }

        // ---- epilogue: gates, c/h update, h store, fc ----
        #pragma unroll
        for (int mt = 0; mt < 2; ++mt) {
            #pragma unroll
            for (int hh = 0; hh < 2; ++hh) {
                float xt = xtv[mt][hh];
                float hv2[2];
                #pragma unroll
                for (int d = 0; d < 2; ++d) {
                    int e = hh * 2 + d;
                    float gi = D[mt][0][e] + bs[0][d] + xt * ws[0][d];
                    float gf = D[mt][1][e] + bs[1][d] + xt * ws[1][d];
                    float gg = D[mt][2][e] + bs[2][d] + xt * ws[2][d];
                    float go = D[mt][3][e] + bs[3][d] + xt * ws[3][d];
                    float c2 = sigm(gf) * cst[mt][e] + sigm(gi) * tanha(gg);
                    cst[mt][e] = c2;
                    hv2[d] = sigm(go) * tanha(c2);
                }
                __half h0 = __float2half_rn(hv2[0]);
                __half h1 = __float2half_rn(hv2[1]);
                uint32_t hiu = (uint32_t)__half_as_ushort(h0) |
                               ((uint32_t)__half_as_ushort(h1) << 16);
                size_t off = (size_t)bth[mt][hh] * 1024 + (size_t)kpos * 2;
                *(uint32_t*)((char*)g_hpack + off) = hiu;

                if (t >= 511) {
                    float pa = hv2[0] * wfc_r[0] + hv2[1] * wfc_r[1];
                    pa += __shfl_xor_sync(0xFFFFFFFFu, pa, 1);
                    pa += __shfl_xor_sync(0xFFFFFFFFu, pa, 2);
                    if (ql == 0)
                        atomicAdd(&g_xdec[(t - 511) * 1024 + bth[mt][hh]], pa);
                }
            }
        }

        // ---- group barrier arrive ----
        __syncthreads();
        if (tid == 0)
            asm volatile("red.release.gpu.global.add.u32 [%0], 1;"
                         :: "l"(cptr) : "memory");
    }
    #undef LOADCHUNK
}

extern "C" void kernel_launch(void* const* d_in, const int* in_sizes, int n_in,
                              void* d_out, int out_size) {
    (void)in_sizes; (void)n_in; (void)out_size;
    cudaFuncSetAttribute(lstm_mma, cudaFuncAttributeMaxDynamicSharedMemorySize,
                         SMEM_MAIN);
    prep_all<<<2048, 256>>>((const float*)d_in[0], (const float*)d_in[2]);
    lstm_mma<<<NCTA, NTHR, SMEM_MAIN>>>(
        (const float*)d_in[1],   // w_ih
        (const float*)d_in[3],   // b_ih
        (const float*)d_in[4],   // b_hh
        (const float*)d_in[5],   // w_fc
        (const float*)d_in[6],   // b_fc
        (float*)d_out);
}

// round 16
// speedup vs baseline: 1.2543x; 1.0084x over previous
#include <cuda_runtime.h>
#include <cuda_fp16.h>
#include <cstdint>

#define NCTA 128
#define NTHR 512
#define OFF_STA 131072                       // after 128KB resident w
#define OFF_MB  (131072 + 4 * 16384)         // mbarriers after 4 A slots
#define SMEM_MAIN (OFF_MB + 128)             // 196736

// ---------------- device scratch ----------------
__device__ __align__(128) unsigned char g_hpack[1048576]; // [b1024][k512] fp16 h
__device__ __align__(128) unsigned char g_wpack[2097152]; // [n2048 perm][k512] fp16 w
__device__ float g_xT[512 * 1024];
__device__ float g_xdec[48 * 1024];
__device__ __align__(128) unsigned g_cnt8[256];   // 8 group counters, 128B apart

__device__ __forceinline__ float tanha(float x) {
    float r;
    asm("tanh.approx.f32 %0, %1;" : "=f"(r) : "f"(x));
    return r;
}
__device__ __forceinline__ float sigm(float x) {
    return fmaf(tanha(0.5f * x), 0.5f, 0.5f);
}
__device__ __forceinline__ void cpa16(unsigned dst, const void* src) {
    asm volatile("cp.async.cg.shared.global [%0], [%1], 16;" :: "r"(dst), "l"(src));
}
__device__ __forceinline__ void ldmx4(uint32_t& r0, uint32_t& r1, uint32_t& r2,
                                      uint32_t& r3, unsigned a) {
    asm volatile("ldmatrix.sync.aligned.m8n8.x4.shared.b16 {%0,%1,%2,%3}, [%4];"
        : "=r"(r0), "=r"(r1), "=r"(r2), "=r"(r3) : "r"(a));
}
__device__ __forceinline__ void mma16816(float* d, const uint32_t* a,
                                         uint32_t b0, uint32_t b1) {
    asm volatile("mma.sync.aligned.m16n8k16.row.col.f32.f16.f16.f32 "
        "{%0,%1,%2,%3}, {%4,%5,%6,%7}, {%8,%9}, {%0,%1,%2,%3};"
        : "+f"(d[0]), "+f"(d[1]), "+f"(d[2]), "+f"(d[3])
        : "r"(a[0]), "r"(a[1]), "r"(a[2]), "r"(a[3]), "r"(b0), "r"(b1));
}

#define MBINIT(a, n) \
    asm volatile("mbarrier.init.shared.b64 [%0], %1;" :: "r"(a), "r"(n) : "memory")
// .noinc is load-bearing: default form raises expected-count by 1 per call and
// the barrier never flips (R15 deadlock).
#define CPA_MBARR(a) \
    asm volatile("cp.async.mbarrier.arrive.noinc.shared::cta.b64 [%0];" \
                 :: "r"(a) : "memory")
#define MB_ARRIVE(a) \
    asm volatile("{\n\t.reg .b64 s;\n\tmbarrier.arrive.shared::cta.b64 s, [%0];\n\t}" \
                 :: "r"(a) : "memory")
#define MBWAIT(mb, ph) do { unsigned _ok;                                     \
    asm volatile("{\n\t.reg .pred p;\n\t"                                     \
        "mbarrier.try_wait.parity.shared::cta.b64 p, [%1], %2;\n\t"           \
        "selp.b32 %0,1,0,p;\n\t}" : "=r"(_ok) : "r"(mb), "r"(ph) : "memory"); \
    while (!_ok) {                                                            \
        asm volatile("{\n\t.reg .pred p;\n\t"                                 \
            "mbarrier.try_wait.parity.shared::cta.b64 p, [%1], %2, 0x989680;\n\t" \
            "selp.b32 %0,1,0,p;\n\t}" : "=r"(_ok) : "r"(mb), "r"(ph) : "memory"); } \
} while (0)

// ---------------- merged prologue kernel ----------------
extern "C" __global__ void prep_all(const float* __restrict__ x,
                                    const float* __restrict__ w_hh) {
    int bid = blockIdx.x, tid = threadIdx.x;
    int n = bid * 256 + tid;                        // 0..524287
    int b = n >> 9, t = n & 511;
    g_xT[t * 1024 + b] = x[n];                      // x[b][t][0]
    if (n < 262144) ((uint32_t*)g_hpack)[n] = 0u;   // zero h plane (1MB)
    if (n < 48 * 1024) g_xdec[n] = 0.f;
    if (n < 256) g_cnt8[n] = 0u;                    // reset group barriers
    int ng = bid;
    int j = ng >> 7, nl = ng & 127;
    int wn = nl >> 5, gate = (nl >> 3) & 3, ul = nl & 7;
    int row = gate * 512 + j * 32 + wn * 8 + ul;
    ((__half*)g_wpack)[(size_t)ng * 512 + tid] =
        __float2half_rn(w_hh[row * 512 + tid]);
    ((__half*)g_wpack)[(size_t)ng * 512 + tid + 256] =
        __float2half_rn(w_hh[row * 512 + tid + 256]);
}

// ---------------- main persistent kernel ----------------
extern "C" __global__ void __launch_bounds__(NTHR, 1)
lstm_mma(const float* __restrict__ w_ih, const float* __restrict__ b_ih,
         const float* __restrict__ b_hh, const float* __restrict__ w_fc,
         const float* __restrict__ b_fc, float* __restrict__ dout)
{
    extern __shared__ __align__(1024) char smem[];
    const unsigned sa = (unsigned)__cvta_generic_to_shared(smem);
    const unsigned mb_full  = sa + OFF_MB;        // 8 x 8B
    const unsigned mb_empty = sa + OFF_MB + 64;   // 4 x 8B

    const int tid = threadIdx.x;
    const int lane = tid & 31, w = tid >> 5;   // 16 warps
    const int wm = w >> 2, wn = w & 3;         // 4x4 warp grid, m32 x n32
    const int ql = lane & 3, qr = lane >> 2;
    const int i = blockIdx.x & 7, j = blockIdx.x >> 3;
    unsigned* const cptr = g_cnt8 + (i << 5);

    // per-thread constants
    float bs[4][2], ws[4][2], wfc_r[2];
    #pragma unroll
    for (int d = 0; d < 2; ++d) {
        int u = j * 32 + wn * 8 + 2 * ql + d;
        wfc_r[d] = w_fc[u];
        #pragma unroll
        for (int g = 0; g < 4; ++g) {
            int row = g * 512 + u;
            bs[g][d] = b_ih[row] + b_hh[row];
            ws[g][d] = w_ih[row];
        }
    }
    const float bfc = b_fc[0];
    int bth[2][2];
    #pragma unroll
    for (int mt = 0; mt < 2; ++mt)
        #pragma unroll
        for (int hh = 0; hh < 2; ++hh)
            bth[mt][hh] = i * 128 + wm * 32 + mt * 16 + qr + 8 * hh;
    const int kpos = j * 32 + wn * 8 + 2 * ql;

    // ---- resident w: 8 panels of [128 rows][64 k] fp16, SW128 swizzled ----
    for (int idx = tid; idx < 8192; idx += NTHR) {
        int c = idx >> 10, r = (idx >> 3) & 127, q = idx & 7;
        unsigned dst = sa + (unsigned)(c * 16384 + r * 128 + ((q ^ (r & 7)) * 16));
        const char* src = (const char*)g_wpack +
            ((size_t)(j * 128 + r)) * 1024 + c * 128 + q * 16;
        cpa16(dst, src);
    }
    asm volatile("cp.async.commit_group;\n\tcp.async.wait_group 0;" ::: "memory");
    if (tid == 0) {
        #pragma unroll
        for (int c = 0; c < 8; ++c) MBINIT(mb_full + c * 8, NTHR);
        #pragma unroll
        for (int s = 0; s < 4; ++s) MBINIT(mb_empty + s * 8, 16);
    }
    __syncthreads();

    // A staging: chunk = 128 rows x 128B (k64); 2x16B per thread
    const int sr = tid >> 2, sq = tid & 3;
    const char* pA0 = (const char*)g_hpack + (size_t)(i * 128 + sr) * 1024 + sq * 32;
    const unsigned sdst = sa + OFF_STA + (unsigned)(sr * 128);
    const unsigned swo0 = (unsigned)((((sq * 2)     ^ (sr & 7))) << 4);
    const unsigned swo1 = (unsigned)((((sq * 2 + 1) ^ (sr & 7))) << 4);

    // ldmatrix thread bases
    const int rl = lane & 15, qsel = lane >> 4, sw7 = rl & 7;
    const unsigned thA = (unsigned)((wm * 32 + rl) * 128);
    const unsigned thB = (unsigned)((wn * 32 + rl) * 128);

    float cst[2][4];
    #pragma unroll
    for (int mt = 0; mt < 2; ++mt)
        #pragma unroll
        for (int e = 0; e < 4; ++e) cst[mt][e] = 0.f;

    for (int t = 0; t < 560; ++t) {
        const unsigned ph = (unsigned)(t & 1);

        // encoder x loads: static data, hoisted above the barrier wait
        float xtv[2][2];
        if (t < 512) {
            #pragma unroll
            for (int mt = 0; mt < 2; ++mt)
                #pragma unroll
                for (int hh = 0; hh < 2; ++hh)
                    xtv[mt][hh] = g_xT[t * 1024 + bth[mt][hh]];
        }

        // ---- group barrier wait ----
        if (t > 0) {
            if (tid == 0) {
                unsigned tgt = (unsigned)(t << 4);
                unsigned v;
                do {
                    asm volatile("ld.acquire.gpu.global.u32 %0, [%1];"
                                 : "=r"(v) : "l"(cptr) : "memory");
                    if (v < tgt) __nanosleep(32);
                } while (v < tgt);
            }
            __syncthreads();
        }

        // stage chunks 0..3 into slots 0..3
        #pragma unroll
        for (int c0 = 0; c0 < 4; ++c0) {
            unsigned db = sdst + (unsigned)(c0 * 16384);
            const char* a0 = pA0 + c0 * 128;
            cpa16(db + swo0, a0);
            cpa16(db + swo1, a0 + 16);
            CPA_MBARR(mb_full + (unsigned)(c0 * 8));
        }

        if (t >= 512) {
            int p = t - 512;
            #pragma unroll
            for (int mt = 0; mt < 2; ++mt)
                #pragma unroll
                for (int hh = 0; hh < 2; ++hh) {
                    xtv[mt][hh] = __ldcg(&g_xdec[p * 1024 + bth[mt][hh]]) + bfc;
                    if (j == 0 && wn == 0 && ql == 0)
                        dout[bth[mt][hh] * 48 + p] = xtv[mt][hh];
                }
            if (t == 559) break;
        }

        float D[2][4][4];
        #pragma unroll
        for (int mt = 0; mt < 2; ++mt)
            #pragma unroll
            for (int nt = 0; nt < 4; ++nt)
                #pragma unroll
                for (int e = 0; e < 4; ++e) D[mt][nt][e] = 0.f;

        // ---- GEMM: 8 k64 chunks, mbarrier ring, NO CTA-wide syncs ----
        #pragma unroll 1
        for (int c = 0; c < 8; ++c) {
            MBWAIT(mb_full + (unsigned)(c * 8), ph);
            const unsigned stA = sa + OFF_STA + (unsigned)((c & 3) * 16384);
            const unsigned stB = sa + (unsigned)(c * 16384);

            // load all fragments first
            uint32_t Af[4][2][4], Bf[4][4][2];
            #pragma unroll
            for (int k16 = 0; k16 < 4; ++k16) {
                unsigned swz = (unsigned)((((k16 * 2 + qsel) ^ sw7)) << 4);
                #pragma unroll
                for (int nb = 0; nb < 2; ++nb) {
                    uint32_t r0, r1, r2, r3;
                    ldmx4(r0, r1, r2, r3, stB + thB + nb * 2048 + swz);
                    Bf[k16][2 * nb][0] = r0; Bf[k16][2 * nb][1] = r2;
                    Bf[k16][2 * nb + 1][0] = r1; Bf[k16][2 * nb + 1][1] = r3;
                }
                #pragma unroll
                for (int mt = 0; mt < 2; ++mt)
                    ldmx4(Af[k16][mt][0], Af[k16][mt][1],
                          Af[k16][mt][2], Af[k16][mt][3],
                          stA + thA + mt * 2048 + swz);
            }
            // slot read complete: signal empty (one arrive per warp)
            if (c < 4 && lane == 0)
                MB_ARRIVE(mb_empty + (unsigned)(c * 8));

            // mma burst (hides other warps' empty arrivals)
            #pragma unroll
            for (int k16 = 0; k16 < 4; ++k16)
                #pragma unroll
                for (int mt = 0; mt < 2; ++mt)
                    #pragma unroll
                    for (int nt = 0; nt < 4; ++nt)
                        mma16816(D[mt][nt], Af[k16][mt],
                                 Bf[k16][nt][0], Bf[k16][nt][1]);

            // refill slot c with chunk c+4
            if (c < 4) {
                MBWAIT(mb_empty + (unsigned)(c * 8), ph);
                unsigned db = sdst + (unsigned)(c * 16384);
                const char* a0 = pA0 + (c + 4) * 128;
                cpa16(db + swo0, a0);
                cpa16(db + swo1, a0 + 16);
                CPA_MBARR(mb_full + (unsigned)((c + 4) * 8));
            }
        }

        // ---- epilogue: gates, c/h update, h store, fc ----
        #pragma unroll
        for (int mt = 0; mt < 2; ++mt) {
            #pragma unroll
            for (int hh = 0; hh < 2; ++hh) {
                float xt = xtv[mt][hh];
                float hv2[2];
                #pragma unroll
                for (int d = 0; d < 2; ++d) {
                    int e = hh * 2 + d;
                    float gi = D[mt][0][e] + bs[0][d] + xt * ws[0][d];
                    float gf = D[mt][1][e] + bs[1][d] + xt * ws[1][d];
                    float gg = D[mt][2][e] + bs[2][d] + xt * ws[2][d];
                    float go = D[mt][3][e] + bs[3][d] + xt * ws[3][d];
                    float c2 = sigm(gf) * cst[mt][e] + sigm(gi) * tanha(gg);
                    cst[mt][e] = c2;
                    hv2[d] = sigm(go) * tanha(c2);
                }
                __half h0 = __float2half_rn(hv2[0]);
                __half h1 = __float2half_rn(hv2[1]);
                uint32_t hiu = (uint32_t)__half_as_ushort(h0) |
                               ((uint32_t)__half_as_ushort(h1) << 16);
                size_t off = (size_t)bth[mt][hh] * 1024 + (size_t)kpos * 2;
                *(uint32_t*)((char*)g_hpack + off) = hiu;

                if (t >= 511) {
                    float pa = hv2[0] * wfc_r[0] + hv2[1] * wfc_r[1];
                    pa += __shfl_xor_sync(0xFFFFFFFFu, pa, 1);
                    pa += __shfl_xor_sync(0xFFFFFFFFu, pa, 2);
                    if (ql == 0)
                        atomicAdd(&g_xdec[(t - 511) * 1024 + bth[mt][hh]], pa);
                }
            }
        }

        // ---- group barrier arrive ----
        __syncthreads();
        if (tid == 0)
            asm volatile("red.release.gpu.global.add.u32 [%0], 1;"
                         :: "l"(cptr) : "memory");
    }
}

extern "C" void kernel_launch(void* const* d_in, const int* in_sizes, int n_in,
                              void* d_out, int out_size) {
    (void)in_sizes; (void)n_in; (void)out_size;
    cudaFuncSetAttribute(lstm_mma, cudaFuncAttributeMaxDynamicSharedMemorySize,
                         SMEM_MAIN);
    prep_all<<<2048, 256>>>((const float*)d_in[0], (const float*)d_in[2]);
    lstm_mma<<<NCTA, NTHR, SMEM_MAIN>>>(
        (const float*)d_in[1],   // w_ih
        (const float*)d_in[3],   // b_ih
        (const float*)d_in[4],   // b_hh
        (const float*)d_in[5],   // w_fc
        (const float*)d_in[6],   // b_fc
        (float*)d_out);
}